// round 1
// baseline (speedup 1.0000x reference)
#include <cuda_runtime.h>
#include <math.h>

// Problem dims (fixed per reference)
constexpr int B_ = 16;
constexpr int L_ = 1024;
constexpr int D_ = 1024;
#define NEGV (-1e10f)

// GEMM tiling
constexpr int BM = 128;
constexpr int BN = 128;
constexpr int BK = 8;
constexpr int TM = 8;
constexpr int TN = 8;

// ---------------- scratch (static device globals; no runtime alloc) --------
__device__ __align__(16) float g_scores[(size_t)B_ * L_ * L_]; // 64 MB (scores -> attn in place)
__device__ __align__(16) float g_c2q[(size_t)B_ * L_ * D_];    // 64 MB
__device__ float g_sc[B_ * L_];
__device__ float g_sq[B_ * L_];
__device__ int   g_mask_is_byte;

// ---------------- mask dtype autodetect ------------------------------------
// bool-as-byte: 0/1 bytes; a '1' will appear at some index p with p%4 != 0
// (mask rows end in runs of ones). int32 little-endian 0/1: bytes at p%4!=0
// are always zero. Scan once, store flag.
__global__ void k_detect(const unsigned char* __restrict__ mask) {
    __shared__ int found;
    if (threadIdx.x == 0) found = 0;
    __syncthreads();
    int any = 0;
    for (int p = threadIdx.x; p < B_ * L_; p += blockDim.x)
        if ((p & 3) && mask[p]) any = 1;
    if (any) atomicOr(&found, 1);
    __syncthreads();
    if (threadIdx.x == 0) g_mask_is_byte = found;
}

__device__ __forceinline__ int mask_at(const void* mask, int idx, int is_byte) {
    if (is_byte) return ((const unsigned char*)mask)[idx] != 0;
    return ((const int*)mask)[idx] != 0;
}

// ---------------- s_c, s_q: per-row dots with w1, w2 ------------------------
__global__ void k_scsq(const float* __restrict__ inp, const float* __restrict__ wsim) {
    int row = blockIdx.x * (blockDim.x >> 5) + (threadIdx.x >> 5);
    if (row >= B_ * L_) return;
    int lane = threadIdx.x & 31;
    const float* x = inp + (size_t)row * D_;
    float s1 = 0.f, s2 = 0.f;
    for (int d = lane; d < D_; d += 32) {
        float v = x[d];
        s1 += v * wsim[d];
        s2 += v * wsim[D_ + d];
    }
    #pragma unroll
    for (int o = 16; o; o >>= 1) {
        s1 += __shfl_xor_sync(0xffffffffu, s1, o);
        s2 += __shfl_xor_sync(0xffffffffu, s2, o);
    }
    if (lane == 0) { g_sc[row] = s1; g_sq[row] = s2; }
}

// ---------------- GEMM1: scores[b,i,j] = sum_d inp[i,d]*w3[d]*inp[j,d] + sc+sq
__global__ __launch_bounds__(256, 2) void k_gemm1(const float* __restrict__ inp,
                                                  const float* __restrict__ wsim) {
    const float* w3 = wsim + 2 * D_;
    int b  = blockIdx.z;
    int bi = blockIdx.y * BM;
    int bj = blockIdx.x * BN;
    const float* Abase = inp + (size_t)b * L_ * D_;

    __shared__ float As[BK][BM];
    __shared__ float Bs[BK][BN];

    int tid  = threadIdx.x;
    int tx   = tid & 15, ty = tid >> 4;
    int lrow = tid >> 1;
    int lcol = (tid & 1) << 2;

    float acc[TM][TN];
    #pragma unroll
    for (int i = 0; i < TM; i++)
        #pragma unroll
        for (int j = 0; j < TN; j++) acc[i][j] = 0.f;

    const float* Aptr = Abase + (size_t)(bi + lrow) * D_ + lcol;
    const float* Bptr = Abase + (size_t)(bj + lrow) * D_ + lcol;

    for (int k0 = 0; k0 < D_; k0 += BK) {
        float4 a4 = *(const float4*)(Aptr + k0);
        float4 b4 = *(const float4*)(Bptr + k0);
        float4 w4 = *(const float4*)(w3 + k0 + lcol);
        a4.x *= w4.x; a4.y *= w4.y; a4.z *= w4.z; a4.w *= w4.w;
        __syncthreads();
        As[lcol + 0][lrow] = a4.x; As[lcol + 1][lrow] = a4.y;
        As[lcol + 2][lrow] = a4.z; As[lcol + 3][lrow] = a4.w;
        Bs[lcol + 0][lrow] = b4.x; Bs[lcol + 1][lrow] = b4.y;
        Bs[lcol + 2][lrow] = b4.z; Bs[lcol + 3][lrow] = b4.w;
        __syncthreads();
        #pragma unroll
        for (int k = 0; k < BK; k++) {
            float ra[TM], rb[TN];
            *(float4*)&ra[0] = *(const float4*)&As[k][ty * TM];
            *(float4*)&ra[4] = *(const float4*)&As[k][ty * TM + 4];
            *(float4*)&rb[0] = *(const float4*)&Bs[k][tx * TN];
            *(float4*)&rb[4] = *(const float4*)&Bs[k][tx * TN + 4];
            #pragma unroll
            for (int i = 0; i < TM; i++)
                #pragma unroll
                for (int j = 0; j < TN; j++)
                    acc[i][j] = fmaf(ra[i], rb[j], acc[i][j]);
        }
    }

    float* C = g_scores + (size_t)b * L_ * L_;
    int gi0 = bi + ty * TM;
    int gj0 = bj + tx * TN;
    float sqv[TN];
    #pragma unroll
    for (int j = 0; j < TN; j++) sqv[j] = g_sq[b * L_ + gj0 + j];
    #pragma unroll
    for (int i = 0; i < TM; i++) {
        float sci = g_sc[b * L_ + gi0 + i];
        #pragma unroll
        for (int j = 0; j < TN; j++) acc[i][j] += sci + sqv[j];
        *(float4*)&C[(size_t)(gi0 + i) * L_ + gj0]     = *(float4*)&acc[i][0];
        *(float4*)&C[(size_t)(gi0 + i) * L_ + gj0 + 4] = *(float4*)&acc[i][4];
    }
}

// ---------------- softmax over j with column mask, in place -----------------
__global__ void k_softmax(const void* __restrict__ mask) {
    __shared__ float redmax[8];
    __shared__ float redsum[8];
    int row = blockIdx.x;          // b*L + i
    int b   = row >> 10;
    int isb = g_mask_is_byte;
    float* s = g_scores + (size_t)row * L_;
    int t = threadIdx.x;

    float4 v = ((const float4*)s)[t];
    int j0 = t << 2;
    int base = b * L_;
    if (mask_at(mask, base + j0 + 0, isb)) v.x = NEGV;
    if (mask_at(mask, base + j0 + 1, isb)) v.y = NEGV;
    if (mask_at(mask, base + j0 + 2, isb)) v.z = NEGV;
    if (mask_at(mask, base + j0 + 3, isb)) v.w = NEGV;

    float mx = fmaxf(fmaxf(v.x, v.y), fmaxf(v.z, v.w));
    #pragma unroll
    for (int o = 16; o; o >>= 1) mx = fmaxf(mx, __shfl_xor_sync(0xffffffffu, mx, o));
    if ((t & 31) == 0) redmax[t >> 5] = mx;
    __syncthreads();
    mx = fmaxf(fmaxf(fmaxf(redmax[0], redmax[1]), fmaxf(redmax[2], redmax[3])),
               fmaxf(fmaxf(redmax[4], redmax[5]), fmaxf(redmax[6], redmax[7])));

    v.x = __expf(v.x - mx); v.y = __expf(v.y - mx);
    v.z = __expf(v.z - mx); v.w = __expf(v.w - mx);
    float sm = v.x + v.y + v.z + v.w;
    #pragma unroll
    for (int o = 16; o; o >>= 1) sm += __shfl_xor_sync(0xffffffffu, sm, o);
    if ((t & 31) == 0) redsum[t >> 5] = sm;
    __syncthreads();
    sm = redsum[0] + redsum[1] + redsum[2] + redsum[3] +
         redsum[4] + redsum[5] + redsum[6] + redsum[7];
    float inv = 1.0f / sm;
    v.x *= inv; v.y *= inv; v.z *= inv; v.w *= inv;
    ((float4*)s)[t] = v;
}

// ---------------- GEMM2: c2q[b] = attn[b] (LxL) @ inp[b] (LxD) --------------
__global__ __launch_bounds__(256, 2) void k_gemm2(const float* __restrict__ inp) {
    int b  = blockIdx.z;
    int bi = blockIdx.y * BM;   // row in L
    int bn = blockIdx.x * BN;   // col in D
    const float* A  = g_scores + (size_t)b * L_ * L_;
    const float* Bm = inp + (size_t)b * L_ * D_;

    __shared__ float As[BK][BM];
    __shared__ float Bs[BK][BN];

    int tid  = threadIdx.x;
    int tx   = tid & 15, ty = tid >> 4;
    int arow = tid >> 1, acol = (tid & 1) << 2;
    int brow = tid >> 5, bcol = (tid & 31) << 2;

    float acc[TM][TN];
    #pragma unroll
    for (int i = 0; i < TM; i++)
        #pragma unroll
        for (int j = 0; j < TN; j++) acc[i][j] = 0.f;

    for (int k0 = 0; k0 < L_; k0 += BK) {
        float4 a4 = *(const float4*)&A[(size_t)(bi + arow) * L_ + k0 + acol];
        float4 b4 = *(const float4*)&Bm[(size_t)(k0 + brow) * D_ + bn + bcol];
        __syncthreads();
        As[acol + 0][arow] = a4.x; As[acol + 1][arow] = a4.y;
        As[acol + 2][arow] = a4.z; As[acol + 3][arow] = a4.w;
        *(float4*)&Bs[brow][bcol] = b4;
        __syncthreads();
        #pragma unroll
        for (int k = 0; k < BK; k++) {
            float ra[TM], rb[TN];
            *(float4*)&ra[0] = *(const float4*)&As[k][ty * TM];
            *(float4*)&ra[4] = *(const float4*)&As[k][ty * TM + 4];
            *(float4*)&rb[0] = *(const float4*)&Bs[k][tx * TN];
            *(float4*)&rb[4] = *(const float4*)&Bs[k][tx * TN + 4];
            #pragma unroll
            for (int i = 0; i < TM; i++)
                #pragma unroll
                for (int j = 0; j < TN; j++)
                    acc[i][j] = fmaf(ra[i], rb[j], acc[i][j]);
        }
    }

    float* C = g_c2q + (size_t)b * L_ * D_;
    int gi0 = bi + ty * TM;
    int gn0 = bn + tx * TN;
    #pragma unroll
    for (int i = 0; i < TM; i++) {
        *(float4*)&C[(size_t)(gi0 + i) * D_ + gn0]     = *(float4*)&acc[i][0];
        *(float4*)&C[(size_t)(gi0 + i) * D_ + gn0 + 4] = *(float4*)&acc[i][4];
    }
}

// ---------------- GEMM3: out = relu([inp,c2q,inp*c2q] @ Wm + bm), masked ----
__global__ __launch_bounds__(256, 2) void k_gemm3(const float* __restrict__ inp,
                                                  const float* __restrict__ Wm,
                                                  const float* __restrict__ bias,
                                                  const void* __restrict__ mask,
                                                  float* __restrict__ out) {
    int bm0 = blockIdx.y * BM;   // global row m in [0, B*L)
    int bn  = blockIdx.x * BN;

    __shared__ float As[BK][BM];
    __shared__ float Bs[BK][BN];

    int tid  = threadIdx.x;
    int tx   = tid & 15, ty = tid >> 4;
    int arow = tid >> 1, acol = (tid & 1) << 2;
    int brow = tid >> 5, bcol = (tid & 31) << 2;

    int m = bm0 + arow;
    const float* inpRow = inp   + (size_t)m * D_;
    const float* c2qRow = g_c2q + (size_t)m * D_;

    float acc[TM][TN];
    #pragma unroll
    for (int i = 0; i < TM; i++)
        #pragma unroll
        for (int j = 0; j < TN; j++) acc[i][j] = 0.f;

    for (int k0 = 0; k0 < 3 * D_; k0 += BK) {
        int kg   = k0 + acol;
        int seg  = kg >> 10;
        int koff = kg & (D_ - 1);
        float4 a4;
        if (seg == 0) {
            a4 = *(const float4*)(inpRow + koff);
        } else if (seg == 1) {
            a4 = *(const float4*)(c2qRow + koff);
        } else {
            float4 x = *(const float4*)(inpRow + koff);
            float4 y = *(const float4*)(c2qRow + koff);
            a4 = make_float4(x.x * y.x, x.y * y.y, x.z * y.z, x.w * y.w);
        }
        float4 b4 = *(const float4*)&Wm[(size_t)(k0 + brow) * D_ + bn + bcol];
        __syncthreads();
        As[acol + 0][arow] = a4.x; As[acol + 1][arow] = a4.y;
        As[acol + 2][arow] = a4.z; As[acol + 3][arow] = a4.w;
        *(float4*)&Bs[brow][bcol] = b4;
        __syncthreads();
        #pragma unroll
        for (int k = 0; k < BK; k++) {
            float ra[TM], rb[TN];
            *(float4*)&ra[0] = *(const float4*)&As[k][ty * TM];
            *(float4*)&ra[4] = *(const float4*)&As[k][ty * TM + 4];
            *(float4*)&rb[0] = *(const float4*)&Bs[k][tx * TN];
            *(float4*)&rb[4] = *(const float4*)&Bs[k][tx * TN + 4];
            #pragma unroll
            for (int i = 0; i < TM; i++)
                #pragma unroll
                for (int j = 0; j < TN; j++)
                    acc[i][j] = fmaf(ra[i], rb[j], acc[i][j]);
        }
    }

    int isb = g_mask_is_byte;
    int gm0 = bm0 + ty * TM;
    int gn0 = bn + tx * TN;
    float bmv[TN];
    #pragma unroll
    for (int j = 0; j < TN; j++) bmv[j] = bias[gn0 + j];
    #pragma unroll
    for (int i = 0; i < TM; i++) {
        int mrow = gm0 + i;
        int mk = mask_at(mask, mrow, isb);
        float r[TN];
        #pragma unroll
        for (int j = 0; j < TN; j++) {
            float z = fmaxf(acc[i][j] + bmv[j], 0.f);
            r[j] = mk ? 0.f : z;
        }
        *(float4*)&out[(size_t)mrow * D_ + gn0]     = *(float4*)&r[0];
        *(float4*)&out[(size_t)mrow * D_ + gn0 + 4] = *(float4*)&r[4];
    }
}

// ---------------- launch -----------------------------------------------------
extern "C" void kernel_launch(void* const* d_in, const int* in_sizes, int n_in,
                              void* d_out, int out_size) {
    const float* inp  = (const float*)d_in[0];
    const void*  mask = d_in[1];
    const float* wsim = (const float*)d_in[2];
    const float* Wm   = (const float*)d_in[3];
    const float* bias = (const float*)d_in[4];
    float* out = (float*)d_out;

    k_detect<<<1, 256>>>((const unsigned char*)mask);
    k_scsq<<<(B_ * L_) / 8, 256>>>(inp, wsim);
    k_gemm1<<<dim3(L_ / BN, L_ / BM, B_), 256>>>(inp, wsim);
    k_softmax<<<B_ * L_, 256>>>(mask);
    k_gemm2<<<dim3(D_ / BN, L_ / BM, B_), 256>>>(inp);
    k_gemm3<<<dim3(D_ / BN, (B_ * L_) / BM), 256>>>(inp, Wm, bias, mask, out);
}

// round 3
// speedup vs baseline: 3.9883x; 3.9883x over previous
#include <cuda_runtime.h>
#include <cstdint>
#include <math.h>

// Problem dims (fixed per reference)
constexpr int B_ = 16;
constexpr int L_ = 1024;
constexpr int D_ = 1024;
#define NEGV (-1e10f)

// ======================= static device scratch ==============================
__device__ __align__(16) float g_scores[(size_t)B_ * L_ * L_]; // scores -> attn (in place)
__device__ __align__(16) float g_c2q[(size_t)B_ * L_ * D_];    // rn(c2q)
__device__ __align__(16) float g_aw[(size_t)B_ * L_ * D_];     // rn(inp * w3)
__device__ __align__(16) float g_inpRN[(size_t)B_ * L_ * D_];  // rn(inp)
__device__ __align__(16) float g_inpT[(size_t)B_ * L_ * D_];   // rn(inp)^T per batch [b][d][j]
__device__ __align__(16) float g_xc[(size_t)B_ * L_ * D_];     // rn(inp * c2q)
__device__ __align__(16) float g_WmT[(size_t)3 * D_ * D_];     // rn(Wm)^T [D, 3D]
__device__ __align__(16) float g_sc[B_ * L_];
__device__ __align__(16) float g_sq[B_ * L_];
__device__ int g_mask_is_byte;

// ======================= small helpers ======================================
__device__ __forceinline__ uint32_t smem_u32(const void* p) {
    uint32_t a;
    asm("{ .reg .u64 t; cvta.to.shared.u64 t, %1; cvt.u32.u64 %0, t; }" : "=r"(a) : "l"(p));
    return a;
}
__device__ __forceinline__ float rn_tf32(float x) {
    uint32_t u;
    asm("cvt.rn.tf32.f32 %0, %1;" : "=r"(u) : "f"(x));
    return __uint_as_float(u);
}
__device__ __forceinline__ void cp16(uint32_t dst, const void* src) {
    asm volatile("cp.async.cg.shared.global [%0], [%1], 16;" :: "r"(dst), "l"(src));
}
__device__ __forceinline__ int mask_at(const void* mask, int idx, int is_byte) {
    if (is_byte) return ((const unsigned char*)mask)[idx] != 0;
    return ((const int*)mask)[idx] != 0;
}
__device__ __forceinline__ void mma_tf32(float* d, const float* a, const float* bf) {
    asm volatile(
        "mma.sync.aligned.m16n8k8.row.col.f32.tf32.tf32.f32 "
        "{%0,%1,%2,%3}, {%4,%5,%6,%7}, {%8,%9}, {%0,%1,%2,%3};"
        : "+f"(d[0]), "+f"(d[1]), "+f"(d[2]), "+f"(d[3])
        : "r"(__float_as_uint(a[0])), "r"(__float_as_uint(a[1])),
          "r"(__float_as_uint(a[2])), "r"(__float_as_uint(a[3])),
          "r"(__float_as_uint(bf[0])), "r"(__float_as_uint(bf[1])));
}

// ======================= mask dtype autodetect ==============================
__global__ void k_detect(const unsigned char* __restrict__ mask) {
    __shared__ int found;
    if (threadIdx.x == 0) found = 0;
    __syncthreads();
    int any = 0;
    for (int p = threadIdx.x; p < B_ * L_; p += blockDim.x)
        if ((p & 3) && mask[p]) any = 1;
    if (any) atomicOr(&found, 1);
    __syncthreads();
    if (threadIdx.x == 0) g_mask_is_byte = found;
}

// ======================= prep: aw, inpRN =====================================
__global__ void k_prep(const float* __restrict__ inp, const float* __restrict__ wsim) {
    int idx = blockIdx.x * blockDim.x + threadIdx.x;      // float4 index
    float4 x = ((const float4*)inp)[idx];
    float4 w = ((const float4*)(wsim + 2 * D_))[idx & 255];
    float4 a, r;
    a.x = rn_tf32(x.x * w.x); a.y = rn_tf32(x.y * w.y);
    a.z = rn_tf32(x.z * w.z); a.w = rn_tf32(x.w * w.w);
    r.x = rn_tf32(x.x); r.y = rn_tf32(x.y); r.z = rn_tf32(x.z); r.w = rn_tf32(x.w);
    ((float4*)g_aw)[idx] = a;
    ((float4*)g_inpRN)[idx] = r;
}

// ======================= s_c, s_q ===========================================
__global__ void k_scsq(const float* __restrict__ inp, const float* __restrict__ wsim) {
    int row = blockIdx.x * (blockDim.x >> 5) + (threadIdx.x >> 5);
    if (row >= B_ * L_) return;
    int lane = threadIdx.x & 31;
    const float* x = inp + (size_t)row * D_;
    float s1 = 0.f, s2 = 0.f;
    for (int d = lane; d < D_; d += 32) {
        float v = x[d];
        s1 += v * wsim[d];
        s2 += v * wsim[D_ + d];
    }
    #pragma unroll
    for (int o = 16; o; o >>= 1) {
        s1 += __shfl_xor_sync(0xffffffffu, s1, o);
        s2 += __shfl_xor_sync(0xffffffffu, s2, o);
    }
    if (lane == 0) { g_sc[row] = s1; g_sq[row] = s2; }
}

// ======================= transposes =========================================
__global__ void k_transpose_inp() {
    __shared__ float t[32][33];
    int b  = blockIdx.z;
    int d0 = blockIdx.x * 32;
    int j0 = blockIdx.y * 32;
    const float* src = g_inpRN + (size_t)b * L_ * D_;
    float* dst = g_inpT + (size_t)b * L_ * D_;
    #pragma unroll
    for (int k = 0; k < 4; k++)
        t[threadIdx.y + 8 * k][threadIdx.x] =
            src[(size_t)(j0 + threadIdx.y + 8 * k) * D_ + d0 + threadIdx.x];
    __syncthreads();
    #pragma unroll
    for (int k = 0; k < 4; k++)
        dst[(size_t)(d0 + threadIdx.y + 8 * k) * L_ + j0 + threadIdx.x] =
            t[threadIdx.x][threadIdx.y + 8 * k];
}

__global__ void k_transpose_wm(const float* __restrict__ Wm) {
    __shared__ float t[32][33];
    int n0 = blockIdx.x * 32;   // col of Wm (D)
    int k0 = blockIdx.y * 32;   // row of Wm (3D)
    #pragma unroll
    for (int k = 0; k < 4; k++)
        t[threadIdx.y + 8 * k][threadIdx.x] =
            rn_tf32(Wm[(size_t)(k0 + threadIdx.y + 8 * k) * D_ + n0 + threadIdx.x]);
    __syncthreads();
    #pragma unroll
    for (int k = 0; k < 4; k++)
        g_WmT[(size_t)(n0 + threadIdx.y + 8 * k) * (3 * D_) + k0 + threadIdx.x] =
            t[threadIdx.x][threadIdx.y + 8 * k];
}

// ======================= softmax (in place, rn output) ======================
__global__ void k_softmax(const void* __restrict__ mask) {
    __shared__ float redmax[8];
    __shared__ float redsum[8];
    int row = blockIdx.x;
    int b   = row >> 10;
    int isb = g_mask_is_byte;
    float* s = g_scores + (size_t)row * L_;
    int t = threadIdx.x;

    float4 v = ((const float4*)s)[t];
    int j0 = t << 2;
    int base = b * L_;
    if (mask_at(mask, base + j0 + 0, isb)) v.x = NEGV;
    if (mask_at(mask, base + j0 + 1, isb)) v.y = NEGV;
    if (mask_at(mask, base + j0 + 2, isb)) v.z = NEGV;
    if (mask_at(mask, base + j0 + 3, isb)) v.w = NEGV;

    float mx = fmaxf(fmaxf(v.x, v.y), fmaxf(v.z, v.w));
    #pragma unroll
    for (int o = 16; o; o >>= 1) mx = fmaxf(mx, __shfl_xor_sync(0xffffffffu, mx, o));
    if ((t & 31) == 0) redmax[t >> 5] = mx;
    __syncthreads();
    mx = fmaxf(fmaxf(fmaxf(redmax[0], redmax[1]), fmaxf(redmax[2], redmax[3])),
               fmaxf(fmaxf(redmax[4], redmax[5]), fmaxf(redmax[6], redmax[7])));

    v.x = __expf(v.x - mx); v.y = __expf(v.y - mx);
    v.z = __expf(v.z - mx); v.w = __expf(v.w - mx);
    float sm = v.x + v.y + v.z + v.w;
    #pragma unroll
    for (int o = 16; o; o >>= 1) sm += __shfl_xor_sync(0xffffffffu, sm, o);
    if ((t & 31) == 0) redsum[t >> 5] = sm;
    __syncthreads();
    sm = redsum[0] + redsum[1] + redsum[2] + redsum[3] +
         redsum[4] + redsum[5] + redsum[6] + redsum[7];
    float inv = 1.0f / sm;
    v.x = rn_tf32(v.x * inv); v.y = rn_tf32(v.y * inv);
    v.z = rn_tf32(v.z * inv); v.w = rn_tf32(v.w * inv);
    ((float4*)s)[t] = v;
}

// ======================= HMMA tf32 GEMM =====================================
// CTA tile M=128, N=128, BK=16. 8 warps (2x4), each 64x32 via m16n8k8.
// SMEM tiles stored [row][k] with row stride 20 floats (pad 4) — conflict-free
// for the m16n8k8 fragment gather (g = lane>>2, t = lane&3). 4-stage cp.async.
// E=1: scores = aw @ inpRN^T (+sc+sq)         [per batch]
// E=2: c2q    = attn @ inpT^T                 [per batch], fused xc epilogue
// E=3: out    = [inpRN|c2q|xc] @ WmT^T (+bias, relu, mask)
constexpr int LDS_ = 20;                        // smem row stride (floats)
constexpr int STAGE_F = 2 * 128 * LDS_;         // floats per stage (A+B) = 5120
constexpr int STAGE_BYTES = STAGE_F * 4;        // 20480
constexpr int SMEM_TOTAL = 4 * STAGE_BYTES;     // 81920

template <int E>
__global__ __launch_bounds__(256, 2)
void k_gemm_mma(const float* __restrict__ bias, const void* __restrict__ mask,
                float* __restrict__ out) {
    extern __shared__ float smem[];
    uint32_t sbase = smem_u32(smem);
    int tid = threadIdx.x;
    int lane = tid & 31, w = tid >> 5;
    int g = lane >> 2, t = lane & 3;
    int wm = w & 1, wn = w >> 1;                 // warp grid 2 (M) x 4 (N)

    constexpr int NCH = (E == 3) ? 192 : 64;     // K chunks of 16
    constexpr int LDB = (E == 3) ? 3072 : 1024;

    int b  = blockIdx.z;
    int i0 = blockIdx.y * 128;
    int n0 = blockIdx.x * 128;

    const float *A0, *A1 = nullptr, *A2 = nullptr, *Bb;
    if (E == 1) {
        A0 = g_aw    + ((size_t)b << 20) + (size_t)i0 * 1024;
        Bb = g_inpRN + ((size_t)b << 20) + (size_t)n0 * 1024;
    } else if (E == 2) {
        A0 = g_scores + ((size_t)b << 20) + (size_t)i0 * 1024;
        Bb = g_inpT   + ((size_t)b << 20) + (size_t)n0 * 1024;
    } else {
        A0 = g_inpRN + (size_t)i0 * 1024;
        A1 = g_c2q   + (size_t)i0 * 1024;
        A2 = g_xc    + (size_t)i0 * 1024;
        Bb = g_WmT   + (size_t)n0 * 3072;
    }

    // load one K-chunk (16 floats wide) into stage s
    auto loadc = [&](int kc, int s) {
        const float* Ab;
        int koff;
        if (E == 3) {
            int seg = kc >> 6;
            koff = (kc & 63) * 16;
            Ab = (seg == 0) ? A0 : (seg == 1) ? A1 : A2;
        } else {
            Ab = A0; koff = kc * 16;
        }
        const float* Bv = Bb + (size_t)kc * 16;
        uint32_t sa = sbase + s * STAGE_BYTES;
        uint32_t sb = sa + 128 * LDS_ * 4;
        // 512 16B chunks each for A and B; 2 per thread each
        #pragma unroll
        for (int r = 0; r < 2; r++) {
            int id = tid + r * 256;
            int row = id >> 2, c4 = id & 3;
            cp16(sa + row * (LDS_ * 4) + c4 * 16, Ab + (size_t)row * 1024 + koff + c4 * 4);
        }
        #pragma unroll
        for (int r = 0; r < 2; r++) {
            int id = tid + r * 256;
            int row = id >> 2, c4 = id & 3;
            cp16(sb + row * (LDS_ * 4) + c4 * 16, Bv + (size_t)row * LDB + c4 * 4);
        }
    };

    float acc[4][4][4];
    #pragma unroll
    for (int i = 0; i < 4; i++)
        #pragma unroll
        for (int j = 0; j < 4; j++)
            #pragma unroll
            for (int q = 0; q < 4; q++) acc[i][j][q] = 0.f;

    // prologue: stages 0..2
    #pragma unroll
    for (int c = 0; c < 3; c++) {
        loadc(c, c);
        asm volatile("cp.async.commit_group;" ::: "memory");
    }

    for (int kc = 0; kc < NCH; kc++) {
        int s = kc & 3;
        asm volatile("cp.async.wait_group 2;" ::: "memory");
        __syncthreads();

        const float* As = smem + s * STAGE_F;
        const float* Bs = As + 128 * LDS_;
        #pragma unroll
        for (int ks = 0; ks < 2; ks++) {
            int kb = ks * 8;
            float af[4][4], bf[4][2];
            #pragma unroll
            for (int mt = 0; mt < 4; mt++) {
                const float* p = As + (wm * 64 + mt * 16 + g) * LDS_ + kb + t;
                af[mt][0] = p[0];
                af[mt][1] = p[8 * LDS_];
                af[mt][2] = p[4];
                af[mt][3] = p[8 * LDS_ + 4];
            }
            #pragma unroll
            for (int nt = 0; nt < 4; nt++) {
                const float* p = Bs + (wn * 32 + nt * 8 + g) * LDS_ + kb + t;
                bf[nt][0] = p[0];
                bf[nt][1] = p[4];
            }
            #pragma unroll
            for (int mt = 0; mt < 4; mt++)
                #pragma unroll
                for (int nt = 0; nt < 4; nt++)
                    mma_tf32(acc[mt][nt], af[mt], bf[nt]);
        }

        int lc = kc + 3;
        if (lc < NCH) loadc(lc, lc & 3);
        asm volatile("cp.async.commit_group;" ::: "memory");
    }

    // ---------------- epilogue ------------------------------------------------
    int isb = (E == 3) ? g_mask_is_byte : 0;
    #pragma unroll
    for (int mt = 0; mt < 4; mt++) {
        int grow0 = i0 + wm * 64 + mt * 16 + g;      // rows grow0, grow0+8
        if (E == 1) {
            float sc0 = g_sc[b * 1024 + grow0];
            float sc1 = g_sc[b * 1024 + grow0 + 8];
            float* c0 = g_scores + ((size_t)b << 20) + (size_t)grow0 * 1024;
            #pragma unroll
            for (int nt = 0; nt < 4; nt++) {
                int gcol = n0 + wn * 32 + nt * 8 + 2 * t;
                float2 sq2 = *(const float2*)(g_sq + b * 1024 + gcol);
                float2 o0 = make_float2(acc[mt][nt][0] + sc0 + sq2.x,
                                        acc[mt][nt][1] + sc0 + sq2.y);
                float2 o1 = make_float2(acc[mt][nt][2] + sc1 + sq2.x,
                                        acc[mt][nt][3] + sc1 + sq2.y);
                *(float2*)(c0 + gcol) = o0;
                *(float2*)(c0 + 8 * 1024 + gcol) = o1;
            }
        } else if (E == 2) {
            size_t base0 = ((size_t)(b * 1024 + grow0)) * 1024;
            #pragma unroll
            for (int nt = 0; nt < 4; nt++) {
                int gcol = n0 + wn * 32 + nt * 8 + 2 * t;
                float2 x0 = *(const float2*)(g_inpRN + base0 + gcol);
                float2 x1 = *(const float2*)(g_inpRN + base0 + 8 * 1024 + gcol);
                float2 c0v = make_float2(rn_tf32(acc[mt][nt][0]), rn_tf32(acc[mt][nt][1]));
                float2 c1v = make_float2(rn_tf32(acc[mt][nt][2]), rn_tf32(acc[mt][nt][3]));
                float2 xc0 = make_float2(rn_tf32(x0.x * c0v.x), rn_tf32(x0.y * c0v.y));
                float2 xc1 = make_float2(rn_tf32(x1.x * c1v.x), rn_tf32(x1.y * c1v.y));
                *(float2*)(g_c2q + base0 + gcol) = c0v;
                *(float2*)(g_c2q + base0 + 8 * 1024 + gcol) = c1v;
                *(float2*)(g_xc + base0 + gcol) = xc0;
                *(float2*)(g_xc + base0 + 8 * 1024 + gcol) = xc1;
            }
        } else {
            int mk0 = mask_at(mask, grow0, isb);
            int mk1 = mask_at(mask, grow0 + 8, isb);
            float* o0 = out + (size_t)grow0 * 1024;
            #pragma unroll
            for (int nt = 0; nt < 4; nt++) {
                int gcol = n0 + wn * 32 + nt * 8 + 2 * t;
                float2 b2 = *(const float2*)(bias + gcol);
                float2 r0, r1;
                r0.x = mk0 ? 0.f : fmaxf(acc[mt][nt][0] + b2.x, 0.f);
                r0.y = mk0 ? 0.f : fmaxf(acc[mt][nt][1] + b2.y, 0.f);
                r1.x = mk1 ? 0.f : fmaxf(acc[mt][nt][2] + b2.x, 0.f);
                r1.y = mk1 ? 0.f : fmaxf(acc[mt][nt][3] + b2.y, 0.f);
                *(float2*)(o0 + gcol) = r0;
                *(float2*)(o0 + 8 * 1024 + gcol) = r1;
            }
        }
    }
}

// ======================= launch =============================================
extern "C" void kernel_launch(void* const* d_in, const int* in_sizes, int n_in,
                              void* d_out, int out_size) {
    const float* inp  = (const float*)d_in[0];
    const void*  mask = d_in[1];
    const float* wsim = (const float*)d_in[2];
    const float* Wm   = (const float*)d_in[3];
    const float* bias = (const float*)d_in[4];
    float* out = (float*)d_out;

    static bool attr_done = false;
    if (!attr_done) {
        cudaFuncSetAttribute(k_gemm_mma<1>, cudaFuncAttributeMaxDynamicSharedMemorySize, SMEM_TOTAL);
        cudaFuncSetAttribute(k_gemm_mma<2>, cudaFuncAttributeMaxDynamicSharedMemorySize, SMEM_TOTAL);
        cudaFuncSetAttribute(k_gemm_mma<3>, cudaFuncAttributeMaxDynamicSharedMemorySize, SMEM_TOTAL);
        attr_done = true;
    }

    k_detect<<<1, 256>>>((const unsigned char*)mask);
    k_prep<<<(B_ * L_ * D_ / 4) / 256, 256>>>(inp, wsim);
    k_scsq<<<(B_ * L_) / 8, 256>>>(inp, wsim);
    k_transpose_inp<<<dim3(32, 32, 16), dim3(32, 8)>>>();
    k_transpose_wm<<<dim3(32, 96), dim3(32, 8)>>>(Wm);

    k_gemm_mma<1><<<dim3(8, 8, 16), 256, SMEM_TOTAL>>>(bias, mask, out);
    k_softmax<<<B_ * L_, 256>>>(mask);
    k_gemm_mma<2><<<dim3(8, 8, 16), 256, SMEM_TOTAL>>>(bias, mask, out);
    k_gemm_mma<3><<<dim3(8, 128, 1), 256, SMEM_TOTAL>>>(bias, mask, out);
}